// round 15
// baseline (speedup 1.0000x reference)
#include <cuda_runtime.h>
#include <cstdint>

// 2x2 Haar inverse reconstruction:
//   x: (32, 4, 512, 512) f32  ->  out: (32, 1, 1024, 1024) f32
//   L0=R*a+R*b; L1=R*a-R*b; H0=R*c+R*d; H1=R*c-R*d
//   out[2h,2w]=R*(L0+H0)  out[2h,2w+1]=R*(L0-H0)
//   out[2h+1,2w]=R*(L1+H1)  out[2h+1,2w+1]=R*(L1-H1)
//
// R15 = R14 + evict-first L2 policy on the bulk store.
// One CTA = one input row (128 threads): 4x LDG.128.cs -> compute ->
// 8KB smem stage (2 output rows) -> one 8KB cp.async.bulk store carrying
// an L2::evict_first cache-policy so the 128MiB write stream drains to
// DRAM promptly instead of thrashing L2 / deferring writebacks.

#define RCONST 0.70710678118654752440f

static constexpr int S = 512;     // input spatial
static constexpr int NIMG = 32;   // batch

__device__ __forceinline__ void haar4(float a, float b, float c, float d,
                                      float& o00, float& o01, float& o10, float& o11) {
    float l0 = RCONST * a + RCONST * b;
    float l1 = RCONST * a - RCONST * b;
    float h0 = RCONST * c + RCONST * d;
    float h1 = RCONST * c - RCONST * d;
    o00 = RCONST * l0 + RCONST * h0;
    o01 = RCONST * l0 - RCONST * h0;
    o10 = RCONST * l1 + RCONST * h1;
    o11 = RCONST * l1 - RCONST * h1;
}

__device__ __forceinline__ uint32_t smem_u32(const void* p) {
    uint32_t a;
    asm("{ .reg .u64 t; cvta.to.shared.u64 t, %1; cvt.u32.u64 %0, t; }"
        : "=r"(a) : "l"(p));
    return a;
}

__global__ __launch_bounds__(128)
void haar_recon_kernel(const float* __restrict__ x, float* __restrict__ out) {
    // 2 output rows x 1024 floats = 8KB
    __shared__ alignas(16) float sout[2 * 2 * S];

    unsigned t  = threadIdx.x;    // 0..127 = wq (float4 index within row)
    unsigned b  = blockIdx.x;
    unsigned h  = b & 511;        // input row
    unsigned n  = b >> 9;         // image

    const size_t cs4 = (size_t)S * S / 4;   // channel stride in float4
    const float4* base = (const float4*)(x + (size_t)n * 4 * S * S + (size_t)h * S) + t;

    // 4 independent 128-bit streaming loads (MLP=4)
    float4 a  = __ldcs(base);
    float4 bb = __ldcs(base + cs4);
    float4 c  = __ldcs(base + 2 * cs4);
    float4 d  = __ldcs(base + 3 * cs4);

    float4 r0a, r0b, r1a, r1b;
    haar4(a.x, bb.x, c.x, d.x, r0a.x, r0a.y, r1a.x, r1a.y);
    haar4(a.y, bb.y, c.y, d.y, r0a.z, r0a.w, r1a.z, r1a.w);
    haar4(a.z, bb.z, c.z, d.z, r0b.x, r0b.y, r1b.x, r1b.y);
    haar4(a.w, bb.w, c.w, d.w, r0b.z, r0b.w, r1b.z, r1b.w);

    // stage: local row 0 = out row 2h, local row 1 = out row 2h+1
    float4* srow0 = (float4*)sout + 2 * t;
    float4* srow1 = (float4*)(sout + 2 * S) + 2 * t;
    srow0[0] = r0a;
    srow0[1] = r0b;
    srow1[0] = r1a;
    srow1[1] = r1b;

    __syncthreads();

    if (t == 0) {
        asm volatile("fence.proxy.async.shared::cta;" ::: "memory");
        // output rows 2h .. 2h+1  (8KB contiguous), evict-first in L2
        float* gdst = out + ((size_t)n * 2 * S + (size_t)2 * h) * (2 * S);
        asm volatile(
            "{\n\t"
            ".reg .b64 pol;\n\t"
            "createpolicy.fractional.L2::evict_first.b64 pol, 1.0;\n\t"
            "cp.async.bulk.global.shared::cta.bulk_group.L2::cache_hint "
            "[%0], [%1], %2, pol;\n\t"
            "}"
            :: "l"(gdst), "r"(smem_u32(sout)),
               "r"((unsigned)(2 * 2 * S * sizeof(float)))
            : "memory");
        asm volatile("cp.async.bulk.commit_group;" ::: "memory");
        asm volatile("cp.async.bulk.wait_group 0;" ::: "memory");
    }
}

extern "C" void kernel_launch(void* const* d_in, const int* in_sizes, int n_in,
                              void* d_out, int out_size) {
    const float* x = (const float*)d_in[0];
    float* out = (float*)d_out;
    // one CTA per (n, input row): 32 * 512 = 16384 CTAs
    haar_recon_kernel<<<NIMG * S, 128>>>(x, out);
}